// round 12
// baseline (speedup 1.0000x reference)
#include <cuda_runtime.h>
#include <cstdint>

// ---------------------------------------------------------------------------
// Heisenberg-collapsed circuit:
//   <Z0> = e2x*e3x + (e0*e1) * (e2y*e3x + e2z)
// Round 12: double-buffered bulk-async. 256 CTAs x 256 threads; each CTA
// issues BOTH 16KB tile loads up front (32KB in flight/CTA), computes tile 0
// while tile 1 streams. Halves per-CTA fixed costs vs R10. K constants via
// PDL-overlapped precompute kernel.
// ---------------------------------------------------------------------------

// K layout (20 floats, 16B aligned; loaded as 5 float4):
//  [0..2]  wire0: C, R, -delta      [3..5]   wire1: C, R, -delta
//  [6..8]  e2x: K0,K1,K2            [9..11]  e2y: K0,K1,K2
//  [12..14]e2z: K0,K1,K2            [15..17] wire3: C, R, -delta
__device__ __align__(16) float g_K[20];

struct Cpx { float r, i; };
__device__ __forceinline__ Cpx cmul(Cpx a, Cpx b) { return {a.r*b.r - a.i*b.i, a.r*b.i + a.i*b.r}; }
__device__ __forceinline__ Cpx cconj(Cpx a)       { return {a.r, -a.i}; }
__device__ __forceinline__ Cpx cadd(Cpx a, Cpx b) { return {a.r + b.r, a.i + b.i}; }
__device__ __forceinline__ Cpx csub(Cpx a, Cpx b) { return {a.r - b.r, a.i - b.i}; }
__device__ __forceinline__ Cpx cmuli(Cpx a)       { return {-a.i, a.r}; }   // i*a

__device__ void rot_mat(const float* __restrict__ w, Cpx R[4]) {
    float phi = w[0], th = w[1], om = w[2];
    float c = cosf(0.5f * th), s = sinf(0.5f * th);
    float a = 0.5f * (phi + om), b = 0.5f * (phi - om);
    Cpx ep = { cosf(a), -sinf(a) };
    Cpx em = { cosf(b),  sinf(b) };
    R[0] = {  ep.r * c,  ep.i * c };
    R[1] = { -em.r * s, -em.i * s };
    R[2] = {  em.r * s, -em.i * s };
    R[3] = {  ep.r * c, -ep.i * c };
}

__device__ void exp_coeffs(const Cpx R[4], int P, float scale, float* K) {
    float N00, N11;
    Cpx N01;
    if (P == 2) {            // Z
        N00 = (R[0].r*R[0].r + R[0].i*R[0].i) - (R[2].r*R[2].r + R[2].i*R[2].i);
        N01 = csub(cmul(cconj(R[0]), R[1]), cmul(cconj(R[2]), R[3]));
        N11 = (R[1].r*R[1].r + R[1].i*R[1].i) - (R[3].r*R[3].r + R[3].i*R[3].i);
    } else if (P == 0) {     // X
        Cpx z02 = cmul(cconj(R[0]), R[2]);
        Cpx z13 = cmul(cconj(R[1]), R[3]);
        N00 = 2.0f * z02.r;
        N01 = cadd(cmul(cconj(R[0]), R[3]), cmul(cconj(R[2]), R[1]));
        N11 = 2.0f * z13.r;
    } else {                 // Y
        Cpx z02 = cmul(cconj(R[0]), R[2]);
        Cpx z13 = cmul(cconj(R[1]), R[3]);
        N00 = 2.0f * z02.i;
        Cpx t1 = cmuli(cmul(cconj(R[0]), R[3]));
        Cpx t2 = cmuli(cmul(cconj(R[2]), R[1]));
        N01 = csub(t2, t1);
        N11 = 2.0f * z13.i;
    }
    K[0] = 0.5f * (N00 + N11) * scale;
    K[1] = 0.5f * (N00 - N11) * scale;
    K[2] = N01.i * scale;
}

__global__ void precompute_k(const float* __restrict__ w) {
    int t = threadIdx.x;
    if (t >= 6) return;

    int wire = (t == 0) ? 0 : (t == 1) ? 1 : (t == 5) ? 3 : 2;
    int P    = (t <= 1) ? 2 : (t == 2) ? 0 : (t == 3) ? 1 : (t == 4) ? 2 : 0;

    float scale = 1.0f;
    if (t >= 2 && t <= 4) {
        Cpx R1[4];
        rot_mat(w + (1 * 4 + 2) * 3, R1);
        float M00 = (R1[0].r*R1[0].r + R1[0].i*R1[0].i)
                  - (R1[2].r*R1[2].r + R1[2].i*R1[2].i);
        Cpx M01 = csub(cmul(cconj(R1[0]), R1[1]), cmul(cconj(R1[2]), R1[3]));
        scale = (t == 2) ? M01.r : (t == 3) ? -M01.i : M00;
    }

    Cpx R[4];
    rot_mat(w + wire * 3, R);
    float K[3];
    exp_coeffs(R, P, scale, K);

    int base = t * 3;
    if (t == 0 || t == 1 || t == 5) {
        float Rm = sqrtf(K[1] * K[1] + K[2] * K[2]);
        float nd = -atan2f(K[2], K[1]);
        g_K[base + 0] = K[0];
        g_K[base + 1] = Rm;
        g_K[base + 2] = nd;
    } else {
        g_K[base + 0] = K[0];
        g_K[base + 1] = K[1];
        g_K[base + 2] = K[2];
    }
    if (t == 0) { g_K[18] = 0.0f; g_K[19] = 0.0f; }
}

__device__ __forceinline__ float eval_sample(float4 xv,
                                             float4 ka, float4 kb, float4 kc,
                                             float4 kd, float4 ke) {
    float e0 = fmaf(ka.y, __cosf(xv.x + ka.z), ka.x);
    float e1 = fmaf(kb.x, __cosf(xv.y + kb.y), ka.w);
    float e3 = fmaf(ke.x, __cosf(xv.w + ke.y), kd.w);
    float s2, c2;
    __sincosf(xv.z, &s2, &c2);
    float e2x = fmaf(kb.w, c2, fmaf(kc.x, s2, kb.z));
    float e2y = fmaf(kc.z, c2, fmaf(kc.w, s2, kc.y));
    float e2z = fmaf(kd.y, c2, fmaf(kd.z, s2, kd.x));
    return fmaf(e0 * e1, fmaf(e2y, e3, e2z), e2x * e3);
}

static constexpr int TILE_SAMPLES = 1024;            // 16 KB per tile
static constexpr int TILE_BYTES   = TILE_SAMPLES * 16;
static constexpr int N_TILES      = 2;               // double buffer
static constexpr int CTA_SAMPLES  = TILE_SAMPLES * N_TILES;   // 2048

__device__ __forceinline__ void mbar_wait_p0(uint32_t mbar_s) {
    uint32_t done;
    asm volatile(
        "{\n\t"
        ".reg .pred p;\n\t"
        "mbarrier.try_wait.parity.acquire.cta.shared::cta.b64 p, [%1], 0;\n\t"
        "selp.b32 %0, 1, 0, p;\n\t"
        "}"
        : "=r"(done) : "r"(mbar_s) : "memory");
    if (!done) {
        asm volatile(
            "{\n\t"
            ".reg .pred P1;\n\t"
            "WAIT_LOOP_%=:\n\t"
            "mbarrier.try_wait.parity.acquire.cta.shared::cta.b64 P1, [%0], 0, 0x989680;\n\t"
            "@P1 bra.uni WAIT_DONE_%=;\n\t"
            "bra.uni WAIT_LOOP_%=;\n\t"
            "WAIT_DONE_%=:\n\t"
            "}"
            :: "r"(mbar_s) : "memory");
    }
}

__global__ __launch_bounds__(256)
void quantum_eval_bulk2(const float* __restrict__ x, float* __restrict__ out) {
    __shared__ __align__(16) float4 tile[N_TILES][TILE_SAMPLES];
    __shared__ uint64_t mbar[N_TILES];

    int tid = threadIdx.x;
    uint32_t tile_s, mbar_s;
    asm("{ .reg .u64 t; cvta.to.shared.u64 t, %1; cvt.u32.u64 %0, t; }"
        : "=r"(tile_s) : "l"(&tile[0][0]));
    asm("{ .reg .u64 t; cvta.to.shared.u64 t, %1; cvt.u32.u64 %0, t; }"
        : "=r"(mbar_s) : "l"(&mbar[0]));

    // Issue BOTH tile loads immediately: 32 KB in flight per CTA.
    if (tid == 0) {
        const float* src = x + (size_t)blockIdx.x * CTA_SAMPLES * 4;
#pragma unroll
        for (int j = 0; j < N_TILES; j++)
            asm volatile("mbarrier.init.shared.b64 [%0], 1;"
                         :: "r"(mbar_s + 8 * j) : "memory");
        asm volatile("fence.proxy.async.shared::cta;" ::: "memory");
#pragma unroll
        for (int j = 0; j < N_TILES; j++) {
            asm volatile("mbarrier.arrive.expect_tx.shared.b64 _, [%0], %1;"
                         :: "r"(mbar_s + 8 * j), "r"((uint32_t)TILE_BYTES) : "memory");
            asm volatile(
                "cp.async.bulk.shared::cta.global.mbarrier::complete_tx::bytes "
                "[%0], [%1], %2, [%3];"
                :: "r"(tile_s + j * TILE_BYTES),
                   "l"(src + (size_t)j * TILE_SAMPLES * 4),
                   "r"((uint32_t)TILE_BYTES),
                   "r"(mbar_s + 8 * j)
                : "memory");
        }
    }

    // Wait for the PDL-overlapped precompute, then fetch K (L1/L2 broadcast).
    cudaGridDependencySynchronize();
    const float4* kp = (const float4*)g_K;
    float4 ka = kp[0];
    float4 kb = kp[1];
    float4 kc = kp[2];
    float4 kd = kp[3];
    float4 ke = kp[4];

    __syncthreads();   // mbar init visible to all before waiting

    float* ob = out + (size_t)blockIdx.x * CTA_SAMPLES;
#pragma unroll
    for (int j = 0; j < N_TILES; j++) {
        mbar_wait_p0(mbar_s + 8 * j);
        // 4 samples/thread, stride 256: conflict-free LDS.128, coalesced STG.
#pragma unroll
        for (int q = 0; q < TILE_SAMPLES / 256; q++) {
            float4 xv = tile[j][q * 256 + tid];
            ob[j * TILE_SAMPLES + q * 256 + tid] =
                eval_sample(xv, ka, kb, kc, kd, ke);
        }
    }
}

extern "C" void kernel_launch(void* const* d_in, const int* in_sizes, int n_in,
                              void* d_out, int out_size) {
    const float* x = (const float*)d_in[0];        // (64, 8192, 4) fp32
    const float* weights = (const float*)d_in[1];  // (2, 4, 3) fp32
    float* out = (float*)d_out;                    // (64, 8192, 1) fp32

    int M = in_sizes[0] / 4;                       // 524288 samples
    int nCTA = M / CTA_SAMPLES;                    // 256 (exact)

    precompute_k<<<1, 32>>>(weights);

    cudaLaunchConfig_t cfg = {};
    cfg.gridDim  = dim3(nCTA, 1, 1);
    cfg.blockDim = dim3(256, 1, 1);
    cfg.dynamicSmemBytes = 0;
    cfg.stream = 0;
    cudaLaunchAttribute attrs[1];
    attrs[0].id = cudaLaunchAttributeProgrammaticStreamSerialization;
    attrs[0].val.programmaticStreamSerializationAllowed = 1;
    cfg.attrs = attrs;
    cfg.numAttrs = 1;

    cudaLaunchKernelEx(&cfg, quantum_eval_bulk2, x, out);
}

// round 13
// speedup vs baseline: 1.0036x; 1.0036x over previous
#include <cuda_runtime.h>
#include <cstdint>

// ---------------------------------------------------------------------------
// Heisenberg-collapsed circuit (final configuration, R10 structure):
//   <Z0> = e2x*e3x + (e0*e1) * (e2y*e3x + e2z)
// - 18 weight-only K constants computed by a tiny 6-thread kernel,
//   overlapped with the eval kernel via Programmatic Dependent Launch.
// - Eval: 512 CTAs x 256 threads; one 16KB cp.async.bulk tile per CTA,
//   4 samples/thread from smem (conflict-free LDS.128, coalesced STG.32).
// - Phase-form trig: wires 0,1,3 use C + R*cos(x + d) (1 MUFU each);
//   wire 2 uses one sincos shared by three affine forms.
// Measured platform floor for this problem: ~8.7 us timed (kernel ~6.3 us);
// all resource axes (FMA/MUFU/issue/occupancy/DRAM BW/in-flight bytes/CTA
// ramp) individually falsified as binders in rounds 2-12.
// ---------------------------------------------------------------------------

// K layout (20 floats, 16B aligned; loaded as 5 float4):
//  [0..2]  wire0: C, R, -delta      [3..5]   wire1: C, R, -delta
//  [6..8]  e2x: K0,K1,K2            [9..11]  e2y: K0,K1,K2
//  [12..14]e2z: K0,K1,K2            [15..17] wire3: C, R, -delta
__device__ __align__(16) float g_K[20];

struct Cpx { float r, i; };
__device__ __forceinline__ Cpx cmul(Cpx a, Cpx b) { return {a.r*b.r - a.i*b.i, a.r*b.i + a.i*b.r}; }
__device__ __forceinline__ Cpx cconj(Cpx a)       { return {a.r, -a.i}; }
__device__ __forceinline__ Cpx cadd(Cpx a, Cpx b) { return {a.r + b.r, a.i + b.i}; }
__device__ __forceinline__ Cpx csub(Cpx a, Cpx b) { return {a.r - b.r, a.i - b.i}; }
__device__ __forceinline__ Cpx cmuli(Cpx a)       { return {-a.i, a.r}; }   // i*a

__device__ void rot_mat(const float* __restrict__ w, Cpx R[4]) {
    float phi = w[0], th = w[1], om = w[2];
    float c = cosf(0.5f * th), s = sinf(0.5f * th);
    float a = 0.5f * (phi + om), b = 0.5f * (phi - om);
    Cpx ep = { cosf(a), -sinf(a) };
    Cpx em = { cosf(b),  sinf(b) };
    R[0] = {  ep.r * c,  ep.i * c };
    R[1] = { -em.r * s, -em.i * s };
    R[2] = {  em.r * s, -em.i * s };
    R[3] = {  ep.r * c, -ep.i * c };
}

__device__ void exp_coeffs(const Cpx R[4], int P, float scale, float* K) {
    float N00, N11;
    Cpx N01;
    if (P == 2) {            // Z
        N00 = (R[0].r*R[0].r + R[0].i*R[0].i) - (R[2].r*R[2].r + R[2].i*R[2].i);
        N01 = csub(cmul(cconj(R[0]), R[1]), cmul(cconj(R[2]), R[3]));
        N11 = (R[1].r*R[1].r + R[1].i*R[1].i) - (R[3].r*R[3].r + R[3].i*R[3].i);
    } else if (P == 0) {     // X
        Cpx z02 = cmul(cconj(R[0]), R[2]);
        Cpx z13 = cmul(cconj(R[1]), R[3]);
        N00 = 2.0f * z02.r;
        N01 = cadd(cmul(cconj(R[0]), R[3]), cmul(cconj(R[2]), R[1]));
        N11 = 2.0f * z13.r;
    } else {                 // Y
        Cpx z02 = cmul(cconj(R[0]), R[2]);
        Cpx z13 = cmul(cconj(R[1]), R[3]);
        N00 = 2.0f * z02.i;
        Cpx t1 = cmuli(cmul(cconj(R[0]), R[3]));
        Cpx t2 = cmuli(cmul(cconj(R[2]), R[1]));
        N01 = csub(t2, t1);
        N11 = 2.0f * z13.i;
    }
    K[0] = 0.5f * (N00 + N11) * scale;
    K[1] = 0.5f * (N00 - N11) * scale;
    K[2] = N01.i * scale;
}

__global__ void precompute_k(const float* __restrict__ w) {
    int t = threadIdx.x;
    if (t >= 6) return;

    // map: 0->(w0,Z) 1->(w1,Z) 2->(w2,X*a) 3->(w2,Y*b) 4->(w2,Z*g) 5->(w3,X)
    int wire = (t == 0) ? 0 : (t == 1) ? 1 : (t == 5) ? 3 : 2;
    int P    = (t <= 1) ? 2 : (t == 2) ? 0 : (t == 3) ? 1 : (t == 4) ? 2 : 0;

    float scale = 1.0f;
    if (t >= 2 && t <= 4) {
        // alpha/beta/gamma from layer-1 wire-2 Rot: M = R^dag Z R
        Cpx R1[4];
        rot_mat(w + (1 * 4 + 2) * 3, R1);
        float M00 = (R1[0].r*R1[0].r + R1[0].i*R1[0].i)
                  - (R1[2].r*R1[2].r + R1[2].i*R1[2].i);
        Cpx M01 = csub(cmul(cconj(R1[0]), R1[1]), cmul(cconj(R1[2]), R1[3]));
        scale = (t == 2) ? M01.r : (t == 3) ? -M01.i : M00;
    }

    Cpx R[4];
    rot_mat(w + wire * 3, R);
    float K[3];
    exp_coeffs(R, P, scale, K);

    int base = t * 3;
    if (t == 0 || t == 1 || t == 5) {
        // phase form: K0 + R*cos(x - delta); store -delta
        float Rm = sqrtf(K[1] * K[1] + K[2] * K[2]);
        float nd = -atan2f(K[2], K[1]);
        g_K[base + 0] = K[0];
        g_K[base + 1] = Rm;
        g_K[base + 2] = nd;
    } else {
        g_K[base + 0] = K[0];
        g_K[base + 1] = K[1];
        g_K[base + 2] = K[2];
    }
    if (t == 0) { g_K[18] = 0.0f; g_K[19] = 0.0f; }
}

__device__ __forceinline__ float eval_sample(float4 xv,
                                             float4 ka, float4 kb, float4 kc,
                                             float4 kd, float4 ke) {
    float e0 = fmaf(ka.y, __cosf(xv.x + ka.z), ka.x);
    float e1 = fmaf(kb.x, __cosf(xv.y + kb.y), ka.w);
    float e3 = fmaf(ke.x, __cosf(xv.w + ke.y), kd.w);
    float s2, c2;
    __sincosf(xv.z, &s2, &c2);
    float e2x = fmaf(kb.w, c2, fmaf(kc.x, s2, kb.z));
    float e2y = fmaf(kc.z, c2, fmaf(kc.w, s2, kc.y));
    float e2z = fmaf(kd.y, c2, fmaf(kd.z, s2, kd.x));
    float t01 = e0 * e1;
    return fmaf(e3, fmaf(t01, e2y, e2x), t01 * e2z);
}

static constexpr int SAMPLES_PER_CTA = 1024;             // 16 KB of float4 x
static constexpr int TILE_BYTES = SAMPLES_PER_CTA * 16;  // 16384

__global__ __launch_bounds__(256)
void quantum_eval_bulk(const float* __restrict__ x, float* __restrict__ out) {
    __shared__ __align__(16) float4 tile[SAMPLES_PER_CTA];
    __shared__ uint64_t mbar;

    int tid = threadIdx.x;
    uint32_t tile_s, mbar_s;
    asm("{ .reg .u64 t; cvta.to.shared.u64 t, %1; cvt.u32.u64 %0, t; }"
        : "=r"(tile_s) : "l"(tile));
    asm("{ .reg .u64 t; cvta.to.shared.u64 t, %1; cvt.u32.u64 %0, t; }"
        : "=r"(mbar_s) : "l"(&mbar));

    // One bulk-async copy brings the whole 16 KB tile into flight at once.
    if (tid == 0) {
        asm volatile("mbarrier.init.shared.b64 [%0], 1;" :: "r"(mbar_s) : "memory");
        asm volatile("fence.proxy.async.shared::cta;" ::: "memory");
        asm volatile("mbarrier.arrive.expect_tx.shared.b64 _, [%0], %1;"
                     :: "r"(mbar_s), "r"((uint32_t)TILE_BYTES) : "memory");
        const float* src = x + (size_t)blockIdx.x * SAMPLES_PER_CTA * 4;
        asm volatile(
            "cp.async.bulk.shared::cta.global.mbarrier::complete_tx::bytes "
            "[%0], [%1], %2, [%3];"
            :: "r"(tile_s), "l"(src), "r"((uint32_t)TILE_BYTES), "r"(mbar_s)
            : "memory");
    }

    // Barrier first (mbar init visibility), overlapping its latency with the
    // PDL grid-dependency wait that follows.
    __syncthreads();

    // Wait for the PDL-overlapped precompute, then fetch K (L1/L2 broadcast).
    cudaGridDependencySynchronize();
    const float4* kp = (const float4*)g_K;
    float4 ka = kp[0];
    float4 kb = kp[1];
    float4 kc = kp[2];
    float4 kd = kp[3];
    float4 ke = kp[4];

    // Wait for the bulk copy (phase 0; smem is fresh every launch).
    {
        uint32_t done;
        asm volatile(
            "{\n\t"
            ".reg .pred p;\n\t"
            "mbarrier.try_wait.parity.acquire.cta.shared::cta.b64 p, [%1], 0;\n\t"
            "selp.b32 %0, 1, 0, p;\n\t"
            "}"
            : "=r"(done) : "r"(mbar_s) : "memory");
        if (!done) {
            asm volatile(
                "{\n\t"
                ".reg .pred P1;\n\t"
                "WAIT_LOOP_%=:\n\t"
                "mbarrier.try_wait.parity.acquire.cta.shared::cta.b64 P1, [%0], 0, 0x989680;\n\t"
                "@P1 bra.uni WAIT_DONE_%=;\n\t"
                "bra.uni WAIT_LOOP_%=;\n\t"
                "WAIT_DONE_%=:\n\t"
                "}"
                :: "r"(mbar_s) : "memory");
        }
    }

    // 4 samples/thread, strided j*256+tid: conflict-free LDS.128, coalesced STG.
    float* ob = out + (size_t)blockIdx.x * SAMPLES_PER_CTA;
#pragma unroll
    for (int j = 0; j < 4; j++) {
        float4 xv = tile[j * 256 + tid];
        ob[j * 256 + tid] = eval_sample(xv, ka, kb, kc, kd, ke);
    }
}

extern "C" void kernel_launch(void* const* d_in, const int* in_sizes, int n_in,
                              void* d_out, int out_size) {
    const float* x = (const float*)d_in[0];        // (64, 8192, 4) fp32
    const float* weights = (const float*)d_in[1];  // (2, 4, 3) fp32
    float* out = (float*)d_out;                    // (64, 8192, 1) fp32

    int M = in_sizes[0] / 4;                       // 524288 samples
    int nCTA = M / SAMPLES_PER_CTA;                // 512 (exact)

    precompute_k<<<1, 32>>>(weights);

    cudaLaunchConfig_t cfg = {};
    cfg.gridDim  = dim3(nCTA, 1, 1);
    cfg.blockDim = dim3(256, 1, 1);
    cfg.dynamicSmemBytes = 0;
    cfg.stream = 0;
    cudaLaunchAttribute attrs[1];
    attrs[0].id = cudaLaunchAttributeProgrammaticStreamSerialization;
    attrs[0].val.programmaticStreamSerializationAllowed = 1;
    cfg.attrs = attrs;
    cfg.numAttrs = 1;

    cudaLaunchKernelEx(&cfg, quantum_eval_bulk, x, out);
}

// round 14
// speedup vs baseline: 1.2903x; 1.2857x over previous
#include <cuda_runtime.h>
#include <cstdint>

// ---------------------------------------------------------------------------
// Heisenberg-collapsed circuit, Round 14: SINGLE kernel.
//   <Z0> = e2x*e3x + (e0*e1) * (e2y*e3x + e2z)
// - 512 CTAs x 256 threads; one 16KB cp.async.bulk tile per CTA.
// - Threads 0-5 compute the six weight-only K triples into smem WHILE the
//   TMA tile is in flight: the K chain (~800cyc incl. atan2f) hides under
//   the tile wait (~1000+cyc), so in-kernel K is ~free — unlike R4 where it
//   was exposed behind a bare __syncthreads.
// - Removes the second graph node entirely (timed-ncu gap: single-kernel
//   ~1.9us vs two-kernel+PDL ~2.35us measured).
// ---------------------------------------------------------------------------

struct Cpx { float r, i; };
__device__ __forceinline__ Cpx cmul(Cpx a, Cpx b) { return {a.r*b.r - a.i*b.i, a.r*b.i + a.i*b.r}; }
__device__ __forceinline__ Cpx cconj(Cpx a)       { return {a.r, -a.i}; }
__device__ __forceinline__ Cpx cadd(Cpx a, Cpx b) { return {a.r + b.r, a.i + b.i}; }
__device__ __forceinline__ Cpx csub(Cpx a, Cpx b) { return {a.r - b.r, a.i - b.i}; }
__device__ __forceinline__ Cpx cmuli(Cpx a)       { return {-a.i, a.r}; }   // i*a

__device__ __forceinline__ void rot_mat(const float* __restrict__ w, Cpx R[4]) {
    float phi = w[0], th = w[1], om = w[2];
    float c, s, epi_n, epr, emi, emr;
    __sincosf(0.5f * th, &s, &c);
    __sincosf(0.5f * (phi + om), &epi_n, &epr);   // ep = (epr, -epi_n)
    __sincosf(0.5f * (phi - om), &emi, &emr);     // em = (emr, +emi)
    R[0] = {  epr * c, -epi_n * c };
    R[1] = { -emr * s, -emi   * s };
    R[2] = {  emr * s, -emi   * s };  // conj(em)*s
    R[3] = {  epr * c,  epi_n * c };  // conj(ep)*c
}

// e = K0 + K1*cos(x) + K2*sin(x) for <v|R^dag P R|v>, v = (cos x/2, -i sin x/2).
__device__ __forceinline__ void exp_coeffs(const Cpx R[4], int P, float scale, float* K) {
    float N00, N11;
    Cpx N01;
    if (P == 2) {            // Z
        N00 = (R[0].r*R[0].r + R[0].i*R[0].i) - (R[2].r*R[2].r + R[2].i*R[2].i);
        N01 = csub(cmul(cconj(R[0]), R[1]), cmul(cconj(R[2]), R[3]));
        N11 = (R[1].r*R[1].r + R[1].i*R[1].i) - (R[3].r*R[3].r + R[3].i*R[3].i);
    } else if (P == 0) {     // X
        Cpx z02 = cmul(cconj(R[0]), R[2]);
        Cpx z13 = cmul(cconj(R[1]), R[3]);
        N00 = 2.0f * z02.r;
        N01 = cadd(cmul(cconj(R[0]), R[3]), cmul(cconj(R[2]), R[1]));
        N11 = 2.0f * z13.r;
    } else {                 // Y
        Cpx z02 = cmul(cconj(R[0]), R[2]);
        Cpx z13 = cmul(cconj(R[1]), R[3]);
        N00 = 2.0f * z02.i;
        Cpx t1 = cmuli(cmul(cconj(R[0]), R[3]));
        Cpx t2 = cmuli(cmul(cconj(R[2]), R[1]));
        N01 = csub(t2, t1);
        N11 = 2.0f * z13.i;
    }
    K[0] = 0.5f * (N00 + N11) * scale;
    K[1] = 0.5f * (N00 - N11) * scale;
    K[2] = N01.i * scale;
}

__device__ __forceinline__ float eval_sample(float4 xv,
                                             float4 ka, float4 kb, float4 kc,
                                             float4 kd, float4 ke) {
    float e0 = fmaf(ka.y, __cosf(xv.x + ka.z), ka.x);
    float e1 = fmaf(kb.x, __cosf(xv.y + kb.y), ka.w);
    float e3 = fmaf(ke.x, __cosf(xv.w + ke.y), kd.w);
    float s2, c2;
    __sincosf(xv.z, &s2, &c2);
    float e2x = fmaf(kb.w, c2, fmaf(kc.x, s2, kb.z));
    float e2y = fmaf(kc.z, c2, fmaf(kc.w, s2, kc.y));
    float e2z = fmaf(kd.y, c2, fmaf(kd.z, s2, kd.x));
    float t01 = e0 * e1;
    return fmaf(e3, fmaf(t01, e2y, e2x), t01 * e2z);
}

static constexpr int SAMPLES_PER_CTA = 1024;             // 16 KB of float4 x
static constexpr int TILE_BYTES = SAMPLES_PER_CTA * 16;  // 16384

__global__ __launch_bounds__(256)
void quantum_fused_tma(const float* __restrict__ x,
                       const float* __restrict__ w,
                       float* __restrict__ out) {
    __shared__ __align__(16) float4 tile[SAMPLES_PER_CTA];
    __shared__ __align__(16) float Ksh[20];
    __shared__ uint64_t mbar;

    int tid = threadIdx.x;
    uint32_t tile_s, mbar_s;
    asm("{ .reg .u64 t; cvta.to.shared.u64 t, %1; cvt.u32.u64 %0, t; }"
        : "=r"(tile_s) : "l"(tile));
    asm("{ .reg .u64 t; cvta.to.shared.u64 t, %1; cvt.u32.u64 %0, t; }"
        : "=r"(mbar_s) : "l"(&mbar));

    // (1) Thread 0: put the whole 16 KB tile in flight immediately.
    if (tid == 0) {
        asm volatile("mbarrier.init.shared.b64 [%0], 1;" :: "r"(mbar_s) : "memory");
        asm volatile("fence.proxy.async.shared::cta;" ::: "memory");
        asm volatile("mbarrier.arrive.expect_tx.shared.b64 _, [%0], %1;"
                     :: "r"(mbar_s), "r"((uint32_t)TILE_BYTES) : "memory");
        const float* src = x + (size_t)blockIdx.x * SAMPLES_PER_CTA * 4;
        asm volatile(
            "cp.async.bulk.shared::cta.global.mbarrier::complete_tx::bytes "
            "[%0], [%1], %2, [%3];"
            :: "r"(tile_s), "l"(src), "r"((uint32_t)TILE_BYTES), "r"(mbar_s)
            : "memory");
    }

    // (2) Threads 0-5: six K triples in parallel, UNDER the TMA in-flight time.
    // map: 0->(w0,Z) 1->(w1,Z) 2->(w2,X*a) 3->(w2,Y*b) 4->(w2,Z*g) 5->(w3,X)
    if (tid < 6) {
        int wire = (tid == 0) ? 0 : (tid == 1) ? 1 : (tid == 5) ? 3 : 2;
        int P    = (tid <= 1) ? 2 : (tid == 2) ? 0 : (tid == 3) ? 1 : (tid == 4) ? 2 : 0;

        float scale = 1.0f;
        if (tid >= 2 && tid <= 4) {
            // alpha/beta/gamma from layer-1 wire-2 Rot: M = R^dag Z R
            Cpx R1[4];
            rot_mat(w + (1 * 4 + 2) * 3, R1);
            float M00 = (R1[0].r*R1[0].r + R1[0].i*R1[0].i)
                      - (R1[2].r*R1[2].r + R1[2].i*R1[2].i);
            Cpx M01 = csub(cmul(cconj(R1[0]), R1[1]), cmul(cconj(R1[2]), R1[3]));
            scale = (tid == 2) ? M01.r : (tid == 3) ? -M01.i : M00;
        }

        Cpx R[4];
        rot_mat(w + wire * 3, R);
        float K[3];
        exp_coeffs(R, P, scale, K);

        int base = tid * 3;
        if (tid == 0 || tid == 1 || tid == 5) {
            // phase form: K0 + R*cos(x - delta); store -delta
            float Rm = sqrtf(K[1] * K[1] + K[2] * K[2]);
            float nd = -atan2f(K[2], K[1]);
            Ksh[base + 0] = K[0];
            Ksh[base + 1] = Rm;
            Ksh[base + 2] = nd;
        } else {
            Ksh[base + 0] = K[0];
            Ksh[base + 1] = K[1];
            Ksh[base + 2] = K[2];
        }
        if (tid == 0) { Ksh[18] = 0.0f; Ksh[19] = 0.0f; }
    }

    // (3) One barrier covers mbar-init AND Ksh visibility.
    __syncthreads();

    // (4) Load K from smem (broadcast LDS.128, ~29cyc) BEFORE the tile wait
    // so it overlaps whatever TMA time remains.
    const float4* kp = (const float4*)Ksh;
    float4 ka = kp[0];
    float4 kb = kp[1];
    float4 kc = kp[2];
    float4 kd = kp[3];
    float4 ke = kp[4];

    // (5) Wait for the bulk copy (phase 0; smem fresh every launch).
    {
        uint32_t done;
        asm volatile(
            "{\n\t"
            ".reg .pred p;\n\t"
            "mbarrier.try_wait.parity.acquire.cta.shared::cta.b64 p, [%1], 0;\n\t"
            "selp.b32 %0, 1, 0, p;\n\t"
            "}"
            : "=r"(done) : "r"(mbar_s) : "memory");
        if (!done) {
            asm volatile(
                "{\n\t"
                ".reg .pred P1;\n\t"
                "WAIT_LOOP_%=:\n\t"
                "mbarrier.try_wait.parity.acquire.cta.shared::cta.b64 P1, [%0], 0, 0x989680;\n\t"
                "@P1 bra.uni WAIT_DONE_%=;\n\t"
                "bra.uni WAIT_LOOP_%=;\n\t"
                "WAIT_DONE_%=:\n\t"
                "}"
                :: "r"(mbar_s) : "memory");
        }
    }

    // (6) 4 samples/thread, stride 256: conflict-free LDS.128, coalesced STG.
    float* ob = out + (size_t)blockIdx.x * SAMPLES_PER_CTA;
#pragma unroll
    for (int j = 0; j < 4; j++) {
        float4 xv = tile[j * 256 + tid];
        ob[j * 256 + tid] = eval_sample(xv, ka, kb, kc, kd, ke);
    }
}

extern "C" void kernel_launch(void* const* d_in, const int* in_sizes, int n_in,
                              void* d_out, int out_size) {
    const float* x = (const float*)d_in[0];        // (64, 8192, 4) fp32
    const float* weights = (const float*)d_in[1];  // (2, 4, 3) fp32
    float* out = (float*)d_out;                    // (64, 8192, 1) fp32

    int M = in_sizes[0] / 4;                       // 524288 samples
    int nCTA = M / SAMPLES_PER_CTA;                // 512 (exact)

    quantum_fused_tma<<<nCTA, 256>>>(x, weights, out);
}

// round 15
// speedup vs baseline: 1.3527x; 1.0483x over previous
#include <cuda_runtime.h>
#include <cstdint>

// ---------------------------------------------------------------------------
// Heisenberg-collapsed circuit, Round 15: single kernel, MORE CTAs.
//   <Z0> = e2x*e3x + (e0*e1) * (e2y*e3x + e2z)
// - 1024 CTAs x 256 threads (best-measured CTA count, R3), 8KB TMA tile per
//   CTA, 2 samples/thread. More independent TMA streams per SM -> better
//   load/compute interleave than 512x16KB (R14: 6.62us kernel).
// - Threads 0-5 compute the six weight-only K triples into smem UNDER the
//   TMA wait; one barrier covers mbar-init + K visibility.
// ---------------------------------------------------------------------------

struct Cpx { float r, i; };
__device__ __forceinline__ Cpx cmul(Cpx a, Cpx b) { return {a.r*b.r - a.i*b.i, a.r*b.i + a.i*b.r}; }
__device__ __forceinline__ Cpx cconj(Cpx a)       { return {a.r, -a.i}; }
__device__ __forceinline__ Cpx cadd(Cpx a, Cpx b) { return {a.r + b.r, a.i + b.i}; }
__device__ __forceinline__ Cpx csub(Cpx a, Cpx b) { return {a.r - b.r, a.i - b.i}; }
__device__ __forceinline__ Cpx cmuli(Cpx a)       { return {-a.i, a.r}; }   // i*a

__device__ __forceinline__ void rot_mat(const float* __restrict__ w, Cpx R[4]) {
    float phi = w[0], th = w[1], om = w[2];
    float c, s, epi_n, epr, emi, emr;
    __sincosf(0.5f * th, &s, &c);
    __sincosf(0.5f * (phi + om), &epi_n, &epr);   // ep = (epr, -epi_n)
    __sincosf(0.5f * (phi - om), &emi, &emr);     // em = (emr, +emi)
    R[0] = {  epr * c, -epi_n * c };
    R[1] = { -emr * s, -emi   * s };
    R[2] = {  emr * s, -emi   * s };  // conj(em)*s
    R[3] = {  epr * c,  epi_n * c };  // conj(ep)*c
}

// e = K0 + K1*cos(x) + K2*sin(x) for <v|R^dag P R|v>, v = (cos x/2, -i sin x/2).
__device__ __forceinline__ void exp_coeffs(const Cpx R[4], int P, float scale, float* K) {
    float N00, N11;
    Cpx N01;
    if (P == 2) {            // Z
        N00 = (R[0].r*R[0].r + R[0].i*R[0].i) - (R[2].r*R[2].r + R[2].i*R[2].i);
        N01 = csub(cmul(cconj(R[0]), R[1]), cmul(cconj(R[2]), R[3]));
        N11 = (R[1].r*R[1].r + R[1].i*R[1].i) - (R[3].r*R[3].r + R[3].i*R[3].i);
    } else if (P == 0) {     // X
        Cpx z02 = cmul(cconj(R[0]), R[2]);
        Cpx z13 = cmul(cconj(R[1]), R[3]);
        N00 = 2.0f * z02.r;
        N01 = cadd(cmul(cconj(R[0]), R[3]), cmul(cconj(R[2]), R[1]));
        N11 = 2.0f * z13.r;
    } else {                 // Y
        Cpx z02 = cmul(cconj(R[0]), R[2]);
        Cpx z13 = cmul(cconj(R[1]), R[3]);
        N00 = 2.0f * z02.i;
        Cpx t1 = cmuli(cmul(cconj(R[0]), R[3]));
        Cpx t2 = cmuli(cmul(cconj(R[2]), R[1]));
        N01 = csub(t2, t1);
        N11 = 2.0f * z13.i;
    }
    K[0] = 0.5f * (N00 + N11) * scale;
    K[1] = 0.5f * (N00 - N11) * scale;
    K[2] = N01.i * scale;
}

__device__ __forceinline__ float eval_sample(float4 xv,
                                             float4 ka, float4 kb, float4 kc,
                                             float4 kd, float4 ke) {
    float e0 = fmaf(ka.y, __cosf(xv.x + ka.z), ka.x);
    float e1 = fmaf(kb.x, __cosf(xv.y + kb.y), ka.w);
    float e3 = fmaf(ke.x, __cosf(xv.w + ke.y), kd.w);
    float s2, c2;
    __sincosf(xv.z, &s2, &c2);
    float e2x = fmaf(kb.w, c2, fmaf(kc.x, s2, kb.z));
    float e2y = fmaf(kc.z, c2, fmaf(kc.w, s2, kc.y));
    float e2z = fmaf(kd.y, c2, fmaf(kd.z, s2, kd.x));
    float t01 = e0 * e1;
    return fmaf(e3, fmaf(t01, e2y, e2x), t01 * e2z);
}

static constexpr int SAMPLES_PER_CTA = 512;              // 8 KB of float4 x
static constexpr int TILE_BYTES = SAMPLES_PER_CTA * 16;  // 8192

__global__ __launch_bounds__(256)
void quantum_fused_tma(const float* __restrict__ x,
                       const float* __restrict__ w,
                       float* __restrict__ out) {
    __shared__ __align__(16) float4 tile[SAMPLES_PER_CTA];
    __shared__ __align__(16) float Ksh[20];
    __shared__ uint64_t mbar;

    int tid = threadIdx.x;
    uint32_t tile_s, mbar_s;
    asm("{ .reg .u64 t; cvta.to.shared.u64 t, %1; cvt.u32.u64 %0, t; }"
        : "=r"(tile_s) : "l"(tile));
    asm("{ .reg .u64 t; cvta.to.shared.u64 t, %1; cvt.u32.u64 %0, t; }"
        : "=r"(mbar_s) : "l"(&mbar));

    // (1) Thread 0: put the whole 8 KB tile in flight immediately.
    if (tid == 0) {
        asm volatile("mbarrier.init.shared.b64 [%0], 1;" :: "r"(mbar_s) : "memory");
        asm volatile("fence.proxy.async.shared::cta;" ::: "memory");
        asm volatile("mbarrier.arrive.expect_tx.shared.b64 _, [%0], %1;"
                     :: "r"(mbar_s), "r"((uint32_t)TILE_BYTES) : "memory");
        const float* src = x + (size_t)blockIdx.x * SAMPLES_PER_CTA * 4;
        asm volatile(
            "cp.async.bulk.shared::cta.global.mbarrier::complete_tx::bytes "
            "[%0], [%1], %2, [%3];"
            :: "r"(tile_s), "l"(src), "r"((uint32_t)TILE_BYTES), "r"(mbar_s)
            : "memory");
    }

    // (2) Threads 0-5: six K triples in parallel, UNDER the TMA in-flight time.
    // map: 0->(w0,Z) 1->(w1,Z) 2->(w2,X*a) 3->(w2,Y*b) 4->(w2,Z*g) 5->(w3,X)
    if (tid < 6) {
        int wire = (tid == 0) ? 0 : (tid == 1) ? 1 : (tid == 5) ? 3 : 2;
        int P    = (tid <= 1) ? 2 : (tid == 2) ? 0 : (tid == 3) ? 1 : (tid == 4) ? 2 : 0;

        float scale = 1.0f;
        if (tid >= 2 && tid <= 4) {
            // alpha/beta/gamma from layer-1 wire-2 Rot: M = R^dag Z R
            Cpx R1[4];
            rot_mat(w + (1 * 4 + 2) * 3, R1);
            float M00 = (R1[0].r*R1[0].r + R1[0].i*R1[0].i)
                      - (R1[2].r*R1[2].r + R1[2].i*R1[2].i);
            Cpx M01 = csub(cmul(cconj(R1[0]), R1[1]), cmul(cconj(R1[2]), R1[3]));
            scale = (tid == 2) ? M01.r : (tid == 3) ? -M01.i : M00;
        }

        Cpx R[4];
        rot_mat(w + wire * 3, R);
        float K[3];
        exp_coeffs(R, P, scale, K);

        int base = tid * 3;
        if (tid == 0 || tid == 1 || tid == 5) {
            // phase form: K0 + R*cos(x - delta); store -delta
            float Rm = sqrtf(K[1] * K[1] + K[2] * K[2]);
            float nd = -atan2f(K[2], K[1]);
            Ksh[base + 0] = K[0];
            Ksh[base + 1] = Rm;
            Ksh[base + 2] = nd;
        } else {
            Ksh[base + 0] = K[0];
            Ksh[base + 1] = K[1];
            Ksh[base + 2] = K[2];
        }
        if (tid == 0) { Ksh[18] = 0.0f; Ksh[19] = 0.0f; }
    }

    // (3) One barrier covers mbar-init AND Ksh visibility.
    __syncthreads();

    // (4) Load K from smem (broadcast LDS.128) before the tile wait.
    const float4* kp = (const float4*)Ksh;
    float4 ka = kp[0];
    float4 kb = kp[1];
    float4 kc = kp[2];
    float4 kd = kp[3];
    float4 ke = kp[4];

    // (5) Wait for the bulk copy (phase 0; smem fresh every launch).
    {
        uint32_t done;
        asm volatile(
            "{\n\t"
            ".reg .pred p;\n\t"
            "mbarrier.try_wait.parity.acquire.cta.shared::cta.b64 p, [%1], 0;\n\t"
            "selp.b32 %0, 1, 0, p;\n\t"
            "}"
            : "=r"(done) : "r"(mbar_s) : "memory");
        if (!done) {
            asm volatile(
                "{\n\t"
                ".reg .pred P1;\n\t"
                "WAIT_LOOP_%=:\n\t"
                "mbarrier.try_wait.parity.acquire.cta.shared::cta.b64 P1, [%0], 0, 0x989680;\n\t"
                "@P1 bra.uni WAIT_DONE_%=;\n\t"
                "bra.uni WAIT_LOOP_%=;\n\t"
                "WAIT_DONE_%=:\n\t"
                "}"
                :: "r"(mbar_s) : "memory");
        }
    }

    // (6) 2 samples/thread, stride 256: conflict-free LDS.128, coalesced STG.
    float* ob = out + (size_t)blockIdx.x * SAMPLES_PER_CTA;
#pragma unroll
    for (int j = 0; j < 2; j++) {
        float4 xv = tile[j * 256 + tid];
        ob[j * 256 + tid] = eval_sample(xv, ka, kb, kc, kd, ke);
    }
}

extern "C" void kernel_launch(void* const* d_in, const int* in_sizes, int n_in,
                              void* d_out, int out_size) {
    const float* x = (const float*)d_in[0];        // (64, 8192, 4) fp32
    const float* weights = (const float*)d_in[1];  // (2, 4, 3) fp32
    float* out = (float*)d_out;                    // (64, 8192, 1) fp32

    int M = in_sizes[0] / 4;                       // 524288 samples
    int nCTA = M / SAMPLES_PER_CTA;                // 1024 (exact)

    quantum_fused_tma<<<nCTA, 256>>>(x, weights, out);
}